// round 1
// baseline (speedup 1.0000x reference)
#include <cuda_runtime.h>
#include <math.h>

// YOLO loss: preds [16384,7,7,30] f32, labels same, scalar f32 out.
// N_CELLS = 16384*49 = 802816 cells of 30 floats each.
// Kernel 1: 6272 blocks x 128 threads, 128 cells/block, smem-staged coalesced
//           loads, per-cell loss, block tree-reduce -> g_partials[block].
// Kernel 2: 1 block, double-precision reduce of 6272 partials -> out = total/N.

#define SIDE 7
#define NBATCH 16384
#define CELLS_PER_BLOCK 128
#define NUM_BLOCKS 6272          // 802816 / 128 exactly
#define FLOATS_PER_CELL 30
#define CHUNK (CELLS_PER_BLOCK * FLOATS_PER_CELL)   // 3840 floats

__device__ float g_partials[NUM_BLOCKS];

__global__ __launch_bounds__(CELLS_PER_BLOCK)
void yolo_main_kernel(const float* __restrict__ preds,
                      const float* __restrict__ labels)
{
    __shared__ float sp[CHUNK];
    __shared__ float sl[CHUNK];

    const int t = threadIdx.x;
    const long long base = (long long)blockIdx.x * CHUNK;

    // Coalesced staging: warp moves 512B contiguous per iteration.
    #pragma unroll
    for (int j = 0; j < FLOATS_PER_CELL; j++) {
        int i = t + j * CELLS_PER_BLOCK;
        sp[i] = preds[base + i];
        sl[i] = labels[base + i];
    }
    __syncthreads();

    const float* p = sp + t * FLOATS_PER_CELL;
    const float* l = sl + t * FLOATS_PER_CELL;

    const float s = 1.0f / (float)SIDE;
    float cell = 0.0f;

    float conf = l[4];
    if (conf == 0.0f) {
        // noobj: 0.5 * sum over both boxes of (pc - lc)^2
        float d0 = p[4] - l[4];
        float d1 = p[9] - l[9];
        cell = 0.5f * (d0 * d0 + d1 * d1);
    } else {
        // label box 0 corners + area
        float l1x = l[0] * s - 0.5f * l[2];
        float l1y = l[1] * s - 0.5f * l[3];
        float l2x = l[0] * s + 0.5f * l[2];
        float l2y = l[1] * s + 0.5f * l[3];
        float la  = l[2] * l[3];

        float iou0, iou1;
        #pragma unroll
        for (int b = 0; b < 2; b++) {
            const float* pb = p + b * 5;
            float p1x = pb[0] * s - 0.5f * pb[2];
            float p1y = pb[1] * s - 0.5f * pb[3];
            float p2x = pb[0] * s + 0.5f * pb[2];
            float p2y = pb[1] * s + 0.5f * pb[3];
            float iw = fmaxf(fminf(p2x, l2x) - fmaxf(p1x, l1x), 0.0f);
            float ih = fmaxf(fminf(p2y, l2y) - fmaxf(p1y, l1y), 0.0f);
            float inter = iw * ih;
            float pa = pb[2] * pb[3];
            float v = inter / (pa + la - inter);
            if (b == 0) iou0 = v; else iou1 = v;
        }

        // jnp.argmax: first max wins -> idx=1 only on strict iou1 > iou0
        int idx = (iou1 > iou0) ? 1 : 0;
        float maxiou = fmaxf(iou0, iou1);

        const float* pr = p + idx * 5;
        const float* lr = l + idx * 5;

        float dresp = pr[4] - maxiou;
        float resp  = dresp * dresp;

        float nrc = p[(1 - idx) * 5 + 4];
        float nr  = nrc * nrc;

        float dx = pr[0] - lr[0];
        float dy = pr[1] - lr[1];
        float xy = dx * dx + dy * dy;

        float dw = sqrtf(pr[2]) - sqrtf(lr[2]);
        float dh = sqrtf(pr[3]) - sqrtf(lr[3]);
        float wh = dw * dw + dh * dh;

        float cls = 0.0f;
        #pragma unroll
        for (int k = 10; k < 30; k++) {
            float d = p[k] - l[k];
            cls += d * d;
        }

        cell = 5.0f * (xy + wh) + 2.0f * resp + nr + cls;
    }

    // Block reduction: warp shuffle tree then cross-warp via smem.
    float v = cell;
    #pragma unroll
    for (int off = 16; off > 0; off >>= 1)
        v += __shfl_down_sync(0xFFFFFFFFu, v, off);

    __shared__ float wsum[CELLS_PER_BLOCK / 32];
    int lane = t & 31;
    int wid  = t >> 5;
    if (lane == 0) wsum[wid] = v;
    __syncthreads();

    if (t == 0) {
        float acc = 0.0f;
        #pragma unroll
        for (int w = 0; w < CELLS_PER_BLOCK / 32; w++) acc += wsum[w];
        g_partials[blockIdx.x] = acc;
    }
}

__global__ __launch_bounds__(256)
void yolo_reduce_kernel(float* __restrict__ out)
{
    double acc = 0.0;
    for (int i = threadIdx.x; i < NUM_BLOCKS; i += 256)
        acc += (double)g_partials[i];

    #pragma unroll
    for (int off = 16; off > 0; off >>= 1)
        acc += __shfl_down_sync(0xFFFFFFFFu, acc, off);

    __shared__ double wsum[8];
    int lane = threadIdx.x & 31;
    int wid  = threadIdx.x >> 5;
    if (lane == 0) wsum[wid] = acc;
    __syncthreads();

    if (threadIdx.x == 0) {
        double total = 0.0;
        #pragma unroll
        for (int w = 0; w < 8; w++) total += wsum[w];
        out[0] = (float)(total / (double)NBATCH);
    }
}

extern "C" void kernel_launch(void* const* d_in, const int* in_sizes, int n_in,
                              void* d_out, int out_size)
{
    const float* preds  = (const float*)d_in[0];
    const float* labels = (const float*)d_in[1];
    float* out = (float*)d_out;

    yolo_main_kernel<<<NUM_BLOCKS, CELLS_PER_BLOCK>>>(preds, labels);
    yolo_reduce_kernel<<<1, 256>>>(out);
}